// round 4
// baseline (speedup 1.0000x reference)
#include <cuda_runtime.h>
#include <cuda_bf16.h>
#include <math.h>

#define BS 16
#define Q 900
#define NC 92
#define TPB 100          // targets per batch
#define NT 1600          // total targets
#define C_ELEMS (16*900*1600)  // 23040000

// transposed per-batch cost slice: ctr[b][t][q]
__device__ float g_ctr[BS * TPB * Q];
__device__ int   g_idmode;   // 1 => tgt_ids stored as int64, 0 => int32

// ---------------------------------------------------------------------------
__global__ void detect_ids_kernel(const unsigned int* __restrict__ ids)
{
    const int tid = threadIdx.x;  // 128
    int ok = 1;
    for (int k = tid; k < 800; k += 128) {
        unsigned lo = ids[2*k], hi = ids[2*k+1];
        if (hi != 0u || lo >= 92u) ok = 0;
    }
    ok = __syncthreads_and(ok);
    if (tid == 0) g_idmode = ok;
}

// ---------------------------------------------------------------------------
// Cost matrix kernel: 8 queries per block, 128 threads.
// ---------------------------------------------------------------------------
#define QPB 8
__global__ void cost_kernel(const float* __restrict__ logits,
                            const float* __restrict__ boxes,
                            const void*  __restrict__ ids,
                            const float* __restrict__ tbox,
                            float* __restrict__ C)
{
    __shared__ float4 s_tb[NT];          // xyxy target boxes
    __shared__ int    s_id[NT];
    __shared__ float  s_prob[QPB][NC];
    __shared__ float  s_box[QPB][4];

    const int tid = threadIdx.x;         // 128
    const int base_bq = blockIdx.x * QPB;
    const int mode = g_idmode;

    const float4* tb4 = (const float4*)tbox;
    for (int x = tid; x < NT; x += 128) s_tb[x] = tb4[x];
    if (mode) {
        const long long* id64 = (const long long*)ids;
        for (int x = tid; x < NT; x += 128) s_id[x] = (int)id64[x];
    } else {
        const int* id32 = (const int*)ids;
        for (int x = tid; x < NT; x += 128) s_id[x] = id32[x];
    }

    const int w = tid >> 5, lane = tid & 31;
    for (int r = w; r < QPB; r += 4) {
        int bq = base_bq + r;
        const float* lr = logits + (size_t)bq * NC;
        float x0 = lr[lane];
        float x1 = lr[lane + 32];
        float x2 = (lane + 64 < NC) ? lr[lane + 64] : -1e30f;
        float m = fmaxf(x0, fmaxf(x1, x2));
        for (int o = 16; o; o >>= 1) m = fmaxf(m, __shfl_xor_sync(~0u, m, o));
        float e0 = expf(x0 - m);
        float e1 = expf(x1 - m);
        float e2 = (lane + 64 < NC) ? expf(x2 - m) : 0.0f;
        float s = e0 + e1 + e2;
        for (int o = 16; o; o >>= 1) s += __shfl_xor_sync(~0u, s, o);
        float inv = 1.0f / s;
        s_prob[r][lane]      = e0 * inv;
        s_prob[r][lane + 32] = e1 * inv;
        if (lane + 64 < NC) s_prob[r][lane + 64] = e2 * inv;
        if (lane < 4) s_box[r][lane] = boxes[(size_t)bq * 4 + lane];
    }
    __syncthreads();

    for (int r = 0; r < QPB; r++) {
        const int bq = base_bq + r;
        const float pcx = s_box[r][0], pcy = s_box[r][1];
        const float pw  = s_box[r][2], ph  = s_box[r][3];
        const float px0 = pcx - pw * 0.5f, py0 = pcy - ph * 0.5f;
        const float px1 = pcx + pw * 0.5f, py1 = pcy + ph * 0.5f;
        const float pa  = (px1 - px0) * (py1 - py0);
        float* Crow = C + (size_t)bq * NT;
        for (int j = tid; j < NT; j += 128) {
            float4 t = s_tb[j];
            float tx0 = t.x, ty0 = t.y, tx1 = t.z, ty1 = t.w;
            float tcx = (tx0 + tx1) * 0.5f, tcy = (ty0 + ty1) * 0.5f;
            float tw = tx1 - tx0, th = ty1 - ty0;
            float cbb = fabsf(pcx - tcx) + fabsf(pcy - tcy)
                      + fabsf(pw - tw) + fabsf(ph - th);
            float ta = tw * th;
            float ix0 = fmaxf(px0, tx0), iy0 = fmaxf(py0, ty0);
            float ix1 = fminf(px1, tx1), iy1 = fminf(py1, ty1);
            float iw = fmaxf(ix1 - ix0, 0.0f), ih = fmaxf(iy1 - iy0, 0.0f);
            float inter = iw * ih;
            float uni = pa + ta - inter;
            float iou = inter / uni;
            float ex0 = fminf(px0, tx0), ey0 = fminf(py0, ty0);
            float ex1 = fmaxf(px1, tx1), ey1 = fmaxf(py1, ty1);
            float cw = fmaxf(ex1 - ex0, 0.0f), ch = fmaxf(ey1 - ey0, 0.0f);
            float ca = cw * ch;
            float giou = iou - (ca - uni) / ca;
            float val = 5.0f * cbb - s_prob[r][s_id[j]] - 2.0f * giou;
            Crow[j] = val;
        }
    }
}

// ---------------------------------------------------------------------------
// Transpose: C[b, q, b*T + t] -> g_ctr[b][t][q]
// ---------------------------------------------------------------------------
__global__ void transpose_kernel(const float* __restrict__ C)
{
    __shared__ float tile[32][33];
    const int b  = blockIdx.z;
    const int q0 = blockIdx.x * 32;
    const int t0 = blockIdx.y * 32;
    int q = q0 + threadIdx.y;
    int t = t0 + threadIdx.x;
    if (q < Q && t < TPB)
        tile[threadIdx.y][threadIdx.x] =
            C[((size_t)(b * Q + q)) * NT + (size_t)b * TPB + t];
    __syncthreads();
    int tt = t0 + threadIdx.y;
    int qq = q0 + threadIdx.x;
    if (tt < TPB && qq < Q)
        g_ctr[b * (TPB * Q) + tt * Q + qq] = tile[threadIdx.x][threadIdx.y];
}

// ---------------------------------------------------------------------------
// Hungarian (JV shortest augmenting path), one block of 128 threads per batch.
// Pure fp64 semantics matching the reference exactly; minimal ops/column:
// scan = 2 DADD + 2 DSETP, update = 1 DADD. One __syncthreads per iteration.
// ---------------------------------------------------------------------------
#define K 8
__global__ void __launch_bounds__(128, 1) lsa_kernel(float* __restrict__ out)
{
    const int b = blockIdx.x;
    const int tid = threadIdx.x;          // 128; column j-1 = tid + k*128
    const int w = tid >> 5, lane = tid & 31;

    __shared__ double u[TPB + 2];
    __shared__ int    p[Q + 2];
    __shared__ int    way[Q + 2];
    __shared__ double s_m[2][4];
    __shared__ int    s_jj[2][4];
    __shared__ int    ans[TPB];

    double v[K];
    int rowof[K];
#pragma unroll
    for (int k = 0; k < K; k++) { v[k] = 0.0; rowof[k] = 0; }

    for (int x = tid; x <= Q; x += 128) p[x] = 0;
    if (tid <= TPB) u[tid] = 0.0;
    __syncthreads();

    const float* cb = g_ctr + b * (TPB * Q);

    for (int i = 1; i <= TPB; i++) {
        if (tid == 0) p[0] = i;
        double minv[K];
        unsigned usedm = 0;
#pragma unroll
        for (int k = 0; k < K; k++) minv[k] = 1e300;

        int i0 = i, j0 = 0;
        double ui0 = 0.0;     // u[i] == 0 the first time row i is processed
        double rd[K];
        {
            const float* crow = cb + (i0 - 1) * Q;
#pragma unroll
            for (int k = 0; k < K; k++) {
                int col = tid + k * 128;
                rd[k] = (col < Q) ? (double)__ldg(&crow[col]) : 0.0;
            }
        }
        int par = 0;

        while (true) {
            // mark column chosen last step as used (owner thread)
            if (j0 >= 1) {
                int idx = j0 - 1;
                if ((idx & 127) == tid) {
                    usedm |= 1u << (idx >> 7);
                    rowof[idx >> 7] = i0;
                }
            }
            // scan my unused columns (pure fp64, strict <, ascending j)
            double lmin = 1e300; int lj = Q + 2;
#pragma unroll
            for (int k = 0; k < K; k++) {
                int col = tid + k * 128;
                if (col < Q && !((usedm >> k) & 1u)) {
                    double cur = (rd[k] - ui0) - v[k];
                    if (cur < minv[k]) { minv[k] = cur; way[col + 1] = j0; }
                    if (minv[k] < lmin) { lmin = minv[k]; lj = col + 1; }
                }
            }
            // warp butterfly (fp64, ties -> smaller j)
            for (int o = 16; o; o >>= 1) {
                double om = __shfl_xor_sync(~0u, lmin, o);
                int    oj = __shfl_xor_sync(~0u, lj, o);
                if (om < lmin || (om == lmin && oj < lj)) { lmin = om; lj = oj; }
            }
            if (lane == 0) { s_m[par][w] = lmin; s_jj[par][w] = lj; }
            __syncthreads();                                   // ONE barrier

            // all threads: final 4-way reduce
            double delta = s_m[par][0]; int j1 = s_jj[par][0];
#pragma unroll
            for (int ww = 1; ww < 4; ww++) {
                double m2 = s_m[par][ww]; int j2 = s_jj[par][ww];
                if (m2 < delta || (m2 == delta && j2 < j1)) { delta = m2; j1 = j2; }
            }
            const int i1 = p[j1];

            // prefetch next row (+convert) and u[i1]; row i1 is untouched by
            // this iteration's u updates, so no race.
            double rd2[K]; double unext = 0.0;
            if (i1 != 0) {
                const float* crow2 = cb + (i1 - 1) * Q;
                float rf[K];
#pragma unroll
                for (int k = 0; k < K; k++) {
                    int col = tid + k * 128;
                    rf[k] = (col < Q) ? __ldg(&crow2[col]) : 0.0f;
                }
                unext = u[i1];
#pragma unroll
                for (int k = 0; k < K; k++) rd2[k] = (double)rf[k];
            }

            // dual updates (reference order; exact fp64)
#pragma unroll
            for (int k = 0; k < K; k++) {
                int col = tid + k * 128;
                if (col < Q) {
                    if ((usedm >> k) & 1u) { v[k] -= delta; u[rowof[k]] += delta; }
                    else                     minv[k] -= delta;
                }
            }
            if (tid == 0) u[i] += delta;   // virtual column 0 (row i)

            if (i1 == 0) {
                if (tid == 0) {
                    int jj = j1;
                    while (jj) { int jp = way[jj]; p[jj] = p[jp]; jj = jp; }
                }
                break;   // ordered before next round by the outer barrier
            }
            j0 = j1; i0 = i1; ui0 = unext;
#pragma unroll
            for (int k = 0; k < K; k++) rd[k] = rd2[k];
            par ^= 1;
        }
        __syncthreads();   // p[] path-walk visible before next round / epilogue
    }

    // ans[t] = matched prediction index for target t
#pragma unroll
    for (int k = 0; k < K; k++) {
        int j = tid + k * 128 + 1;
        if (j <= Q && p[j] > 0) ans[p[j] - 1] = j - 1;
    }
    __syncthreads();
    if (tid < TPB) {
        int a = ans[tid];
        int rank = 0;
        for (int t2 = 0; t2 < TPB; t2++) rank += (ans[t2] < a) ? 1 : 0;
        out[(size_t)C_ELEMS + (size_t)b * TPB + rank]                    = (float)a;
        out[(size_t)C_ELEMS + (size_t)BS * TPB + (size_t)b * TPB + rank] = (float)tid;
    }
}

// ---------------------------------------------------------------------------
extern "C" void kernel_launch(void* const* d_in, const int* in_sizes, int n_in,
                              void* d_out, int out_size)
{
    const float* logits = (const float*)d_in[0];
    const float* boxes  = (const float*)d_in[1];
    const void*  ids    = d_in[2];
    const float* tbox   = (const float*)d_in[3];
    float* out = (float*)d_out;

    detect_ids_kernel<<<1, 128>>>((const unsigned int*)ids);
    cost_kernel<<<(BS * Q) / QPB, 128>>>(logits, boxes, ids, tbox, out);
    dim3 tgrid((Q + 31) / 32, (TPB + 31) / 32, BS);
    transpose_kernel<<<tgrid, dim3(32, 32)>>>(out);
    lsa_kernel<<<BS, 128>>>(out);
}

// round 5
// speedup vs baseline: 1.1562x; 1.1562x over previous
#include <cuda_runtime.h>
#include <cuda_bf16.h>
#include <math.h>

#define BS 16
#define Q 900
#define NC 92
#define TPB 100          // targets per batch
#define NT 1600          // total targets
#define C_ELEMS (16*900*1600)  // 23040000

// transposed per-batch cost slice: ctr[b][t][q]
__device__ float g_ctr[BS * TPB * Q];
__device__ int   g_idmode;   // 1 => tgt_ids stored as int64, 0 => int32

// ---------------------------------------------------------------------------
__global__ void detect_ids_kernel(const unsigned int* __restrict__ ids)
{
    const int tid = threadIdx.x;  // 128
    int ok = 1;
    for (int k = tid; k < 800; k += 128) {
        unsigned lo = ids[2*k], hi = ids[2*k+1];
        if (hi != 0u || lo >= 92u) ok = 0;
    }
    ok = __syncthreads_and(ok);
    if (tid == 0) g_idmode = ok;
}

// ---------------------------------------------------------------------------
// Cost matrix kernel: 8 queries per block, 128 threads.
// ---------------------------------------------------------------------------
#define QPB 8
__global__ void cost_kernel(const float* __restrict__ logits,
                            const float* __restrict__ boxes,
                            const void*  __restrict__ ids,
                            const float* __restrict__ tbox,
                            float* __restrict__ C)
{
    __shared__ float4 s_tb[NT];
    __shared__ int    s_id[NT];
    __shared__ float  s_prob[QPB][NC];
    __shared__ float  s_box[QPB][4];

    const int tid = threadIdx.x;         // 128
    const int base_bq = blockIdx.x * QPB;
    const int mode = g_idmode;

    const float4* tb4 = (const float4*)tbox;
    for (int x = tid; x < NT; x += 128) s_tb[x] = tb4[x];
    if (mode) {
        const long long* id64 = (const long long*)ids;
        for (int x = tid; x < NT; x += 128) s_id[x] = (int)id64[x];
    } else {
        const int* id32 = (const int*)ids;
        for (int x = tid; x < NT; x += 128) s_id[x] = id32[x];
    }

    const int w = tid >> 5, lane = tid & 31;
    for (int r = w; r < QPB; r += 4) {
        int bq = base_bq + r;
        const float* lr = logits + (size_t)bq * NC;
        float x0 = lr[lane];
        float x1 = lr[lane + 32];
        float x2 = (lane + 64 < NC) ? lr[lane + 64] : -1e30f;
        float m = fmaxf(x0, fmaxf(x1, x2));
        for (int o = 16; o; o >>= 1) m = fmaxf(m, __shfl_xor_sync(~0u, m, o));
        float e0 = expf(x0 - m);
        float e1 = expf(x1 - m);
        float e2 = (lane + 64 < NC) ? expf(x2 - m) : 0.0f;
        float s = e0 + e1 + e2;
        for (int o = 16; o; o >>= 1) s += __shfl_xor_sync(~0u, s, o);
        float inv = 1.0f / s;
        s_prob[r][lane]      = e0 * inv;
        s_prob[r][lane + 32] = e1 * inv;
        if (lane + 64 < NC) s_prob[r][lane + 64] = e2 * inv;
        if (lane < 4) s_box[r][lane] = boxes[(size_t)bq * 4 + lane];
    }
    __syncthreads();

    for (int r = 0; r < QPB; r++) {
        const int bq = base_bq + r;
        const float pcx = s_box[r][0], pcy = s_box[r][1];
        const float pw  = s_box[r][2], ph  = s_box[r][3];
        const float px0 = pcx - pw * 0.5f, py0 = pcy - ph * 0.5f;
        const float px1 = pcx + pw * 0.5f, py1 = pcy + ph * 0.5f;
        const float pa  = (px1 - px0) * (py1 - py0);
        float* Crow = C + (size_t)bq * NT;
        for (int j = tid; j < NT; j += 128) {
            float4 t = s_tb[j];
            float tx0 = t.x, ty0 = t.y, tx1 = t.z, ty1 = t.w;
            float tcx = (tx0 + tx1) * 0.5f, tcy = (ty0 + ty1) * 0.5f;
            float tw = tx1 - tx0, th = ty1 - ty0;
            float cbb = fabsf(pcx - tcx) + fabsf(pcy - tcy)
                      + fabsf(pw - tw) + fabsf(ph - th);
            float ta = tw * th;
            float ix0 = fmaxf(px0, tx0), iy0 = fmaxf(py0, ty0);
            float ix1 = fminf(px1, tx1), iy1 = fminf(py1, ty1);
            float iw = fmaxf(ix1 - ix0, 0.0f), ih = fmaxf(iy1 - iy0, 0.0f);
            float inter = iw * ih;
            float uni = pa + ta - inter;
            float iou = inter / uni;
            float ex0 = fminf(px0, tx0), ey0 = fminf(py0, ty0);
            float ex1 = fmaxf(px1, tx1), ey1 = fmaxf(py1, ty1);
            float cw = fmaxf(ex1 - ex0, 0.0f), ch = fmaxf(ey1 - ey0, 0.0f);
            float ca = cw * ch;
            float giou = iou - (ca - uni) / ca;
            float val = 5.0f * cbb - s_prob[r][s_id[j]] - 2.0f * giou;
            Crow[j] = val;
        }
    }
}

// ---------------------------------------------------------------------------
// Transpose: C[b, q, b*T + t] -> g_ctr[b][t][q]
// ---------------------------------------------------------------------------
__global__ void transpose_kernel(const float* __restrict__ C)
{
    __shared__ float tile[32][33];
    const int b  = blockIdx.z;
    const int q0 = blockIdx.x * 32;
    const int t0 = blockIdx.y * 32;
    int q = q0 + threadIdx.y;
    int t = t0 + threadIdx.x;
    if (q < Q && t < TPB)
        tile[threadIdx.y][threadIdx.x] =
            C[((size_t)(b * Q + q)) * NT + (size_t)b * TPB + t];
    __syncthreads();
    int tt = t0 + threadIdx.y;
    int qq = q0 + threadIdx.x;
    if (tt < TPB && qq < Q)
        g_ctr[b * (TPB * Q) + tt * Q + qq] = tile[threadIdx.x][threadIdx.y];
}

// ---------------------------------------------------------------------------
// Order-preserving double <-> uint64 encoding (ascending), -0 canonicalized.
// ---------------------------------------------------------------------------
__device__ __forceinline__ unsigned long long enc64(double x)
{
    long long b = __double_as_longlong(x);
    if ((b << 1) == 0) b = 0;   // canonicalize -0.0 -> +0.0
    return (unsigned long long)(b ^ ((b >> 63) | 0x8000000000000000LL));
}
__device__ __forceinline__ double dec64(unsigned long long e)
{
    long long b = (long long)e;
    b ^= ((~b) >> 63) | 0x8000000000000000LL;
    return __longlong_as_double(b);
}

// ---------------------------------------------------------------------------
// Hungarian (JV), one block of 128 threads per batch. Int-key comparisons,
// REDUX warp argmin, early 4-candidate row prefetch, round-pipelined first-row
// prefetch. One __syncthreads per inner iteration.
// ---------------------------------------------------------------------------
#define K 8
__global__ void __launch_bounds__(128, 1) lsa_kernel(float* __restrict__ out)
{
    const int b = blockIdx.x;
    const int tid = threadIdx.x;          // 128; column j-1 = tid + k*128
    const int w = tid >> 5, lane = tid & 31;

    __shared__ double u[TPB + 2];
    __shared__ int    p[Q + 2];
    __shared__ int    way[Q + 2];
    __shared__ unsigned long long s_em[2][4];
    __shared__ int    s_j[2][4];
    __shared__ int    s_p[2][4];
    __shared__ int    ans[TPB];

    double v[K];
    int rowof[K];
    int cols[K];
#pragma unroll
    for (int k = 0; k < K; k++) { v[k] = 0.0; rowof[k] = 0; cols[k] = tid + k * 128; }

    for (int x = tid; x <= Q; x += 128) p[x] = 0;
    if (tid <= TPB) u[tid] = 0.0;
    __syncthreads();

    const float* cb = g_ctr + b * (TPB * Q);
    const unsigned long long ENC_INF = enc64(1e300);

    // prefetch round 1's row (row index 0)
    float nxt[K];
#pragma unroll
    for (int k = 0; k < K; k++)
        nxt[k] = (cols[k] < Q) ? __ldg(&cb[cols[k]]) : 0.0f;

    int par = 0;

    for (int i = 1; i <= TPB; i++) {
        if (tid == 0) p[0] = i;
        double minv[K];
        unsigned long long em[K];
        unsigned usedm = 0;
#pragma unroll
        for (int k = 0; k < K; k++) { minv[k] = 1e300; em[k] = ENC_INF; }

        int i0 = i, j0 = 0;
        double ui0 = 0.0;     // u[i] == 0 the first time row i is processed
        double rd[K];
#pragma unroll
        for (int k = 0; k < K; k++) rd[k] = (double)nxt[k];

        // prefetch next round's first row during this round
        if (i < TPB) {
            const float* crn = cb + i * Q;   // 0-based row i = round (i+1)'s row
#pragma unroll
            for (int k = 0; k < K; k++)
                nxt[k] = (cols[k] < Q) ? __ldg(&crn[cols[k]]) : 0.0f;
        }

        while (true) {
            // mark column chosen last step as used (owner thread)
            if (j0 >= 1) {
                int idx = j0 - 1;
                if ((idx & 127) == tid) {
                    usedm |= 1u << (idx >> 7);
                    rowof[idx >> 7] = i0;
                }
            }
            // scan my unused columns (fp64 arith, integer compares)
            unsigned long long bestE = ~0ULL; int bestJ = Q + 2;
#pragma unroll
            for (int k = 0; k < K; k++) {
                if (cols[k] < Q && !((usedm >> k) & 1u)) {
                    double cur = (rd[k] - ui0) - v[k];
                    unsigned long long ce = enc64(cur);
                    if (ce < em[k]) { em[k] = ce; minv[k] = cur; way[cols[k] + 1] = j0; }
                    if (em[k] < bestE) { bestE = em[k]; bestJ = cols[k] + 1; }
                    else if (em[k] == bestE && cols[k] + 1 < bestJ) bestJ = cols[k] + 1;
                }
            }
            // warp argmin via 3-stage REDUX (exact 64-bit key, smallest j)
            unsigned hi  = (unsigned)(bestE >> 32);
            unsigned mhi = __reduce_min_sync(0xffffffffu, hi);
            unsigned lo  = (hi == mhi) ? (unsigned)bestE : 0xffffffffu;
            unsigned mlo = __reduce_min_sync(0xffffffffu, lo);
            unsigned cj  = (hi == mhi && (unsigned)bestE == mlo)
                           ? (unsigned)bestJ : 0x7fffffffu;
            unsigned mj  = __reduce_min_sync(0xffffffffu, cj);
            unsigned long long wem = ((unsigned long long)mhi << 32) | mlo;
            int wj = (int)mj;

            if (lane == 0) {
                s_em[par][w] = wem;
                s_j[par][w]  = wj;
                s_p[par][w]  = p[wj];
            }
            __syncthreads();                                   // ONE barrier

            // read the 4 candidates
            unsigned long long ce0 = s_em[par][0], ce1 = s_em[par][1],
                               ce2 = s_em[par][2], ce3 = s_em[par][3];
            int cj0 = s_j[par][0], cj1 = s_j[par][1],
                cj2 = s_j[par][2], cj3 = s_j[par][3];
            int cp0 = s_p[par][0], cp1 = s_p[par][1],
                cp2 = s_p[par][2], cp3 = s_p[par][3];

            // issue candidate-row prefetches IMMEDIATELY (before the reduce)
            float rf0[K], rf1[K], rf2[K], rf3[K];
            if (cp0) { const float* cr = cb + (cp0 - 1) * Q;
#pragma unroll
                for (int k = 0; k < K; k++) rf0[k] = (cols[k] < Q) ? __ldg(&cr[cols[k]]) : 0.0f; }
            if (cp1) { const float* cr = cb + (cp1 - 1) * Q;
#pragma unroll
                for (int k = 0; k < K; k++) rf1[k] = (cols[k] < Q) ? __ldg(&cr[cols[k]]) : 0.0f; }
            if (cp2) { const float* cr = cb + (cp2 - 1) * Q;
#pragma unroll
                for (int k = 0; k < K; k++) rf2[k] = (cols[k] < Q) ? __ldg(&cr[cols[k]]) : 0.0f; }
            if (cp3) { const float* cr = cb + (cp3 - 1) * Q;
#pragma unroll
                for (int k = 0; k < K; k++) rf3[k] = (cols[k] < Q) ? __ldg(&cr[cols[k]]) : 0.0f; }

            // final 4-way reduce (integer, ties -> smaller j); track winner warp
            unsigned long long de = ce0; int j1 = cj0, i1 = cp0, ww = 0;
            if (ce1 < de || (ce1 == de && cj1 < j1)) { de = ce1; j1 = cj1; i1 = cp1; ww = 1; }
            if (ce2 < de || (ce2 == de && cj2 < j1)) { de = ce2; j1 = cj2; i1 = cp2; ww = 2; }
            if (ce3 < de || (ce3 == de && cj3 < j1)) { de = ce3; j1 = cj3; i1 = cp3; ww = 3; }
            const double delta = dec64(de);

            // u[i1] is untouched by this iteration's updates (i1 not matched
            // to any used column), so this unordered read is safe.
            double unext = (i1 != 0) ? u[i1] : 0.0;

            // dual updates (reference order; exact fp64)
#pragma unroll
            for (int k = 0; k < K; k++) {
                if (cols[k] < Q) {
                    if ((usedm >> k) & 1u) { v[k] -= delta; u[rowof[k]] += delta; }
                    else {
                        minv[k] -= delta;
                        em[k] = enc64(minv[k]);
                    }
                }
            }
            if (tid == 0) u[i] += delta;   // virtual column 0 (row i)

            if (i1 == 0) {
                if (tid == 0) {
                    int jj = j1;
                    while (jj) { int jp = way[jj]; p[jj] = p[jp]; jj = jp; }
                }
                par ^= 1;
                break;   // ordered before next round by the outer barrier
            }

            // select winner row's registers
#pragma unroll
            for (int k = 0; k < K; k++) {
                float rw = rf0[k];
                if (ww == 1) rw = rf1[k];
                if (ww == 2) rw = rf2[k];
                if (ww == 3) rw = rf3[k];
                rd[k] = (double)rw;
            }
            j0 = j1; i0 = i1; ui0 = unext;
            par ^= 1;
        }
        __syncthreads();   // p[] path-walk visible before next round / epilogue
    }

    // ans[t] = matched prediction index for target t
#pragma unroll
    for (int k = 0; k < K; k++) {
        int j = cols[k] + 1;
        if (j <= Q && p[j] > 0) ans[p[j] - 1] = j - 1;
    }
    __syncthreads();
    if (tid < TPB) {
        int a = ans[tid];
        int rank = 0;
        for (int t2 = 0; t2 < TPB; t2++) rank += (ans[t2] < a) ? 1 : 0;
        out[(size_t)C_ELEMS + (size_t)b * TPB + rank]                    = (float)a;
        out[(size_t)C_ELEMS + (size_t)BS * TPB + (size_t)b * TPB + rank] = (float)tid;
    }
}

// ---------------------------------------------------------------------------
extern "C" void kernel_launch(void* const* d_in, const int* in_sizes, int n_in,
                              void* d_out, int out_size)
{
    const float* logits = (const float*)d_in[0];
    const float* boxes  = (const float*)d_in[1];
    const void*  ids    = d_in[2];
    const float* tbox   = (const float*)d_in[3];
    float* out = (float*)d_out;

    detect_ids_kernel<<<1, 128>>>((const unsigned int*)ids);
    cost_kernel<<<(BS * Q) / QPB, 128>>>(logits, boxes, ids, tbox, out);
    dim3 tgrid((Q + 31) / 32, (TPB + 31) / 32, BS);
    transpose_kernel<<<tgrid, dim3(32, 32)>>>(out);
    lsa_kernel<<<BS, 128>>>(out);
}

// round 6
// speedup vs baseline: 1.2543x; 1.0848x over previous
#include <cuda_runtime.h>
#include <cuda_bf16.h>
#include <math.h>

#define BS 16
#define Q 900
#define NC 92
#define TPB 100          // targets per batch
#define NT 1600          // total targets
#define C_ELEMS (16*900*1600)  // 23040000
#define ROW_F4 (Q/4)     // 225 float4 per row

// transposed per-batch cost slice, 16B-aligned for float4 loads
__device__ float4 g_ctr4[BS * TPB * ROW_F4];
__device__ int    g_idmode;

// ---------------------------------------------------------------------------
__global__ void detect_ids_kernel(const unsigned int* __restrict__ ids)
{
    const int tid = threadIdx.x;  // 128
    int ok = 1;
    for (int k = tid; k < 800; k += 128) {
        unsigned lo = ids[2*k], hi = ids[2*k+1];
        if (hi != 0u || lo >= 92u) ok = 0;
    }
    ok = __syncthreads_and(ok);
    if (tid == 0) g_idmode = ok;
}

// ---------------------------------------------------------------------------
#define QPB 8
__global__ void cost_kernel(const float* __restrict__ logits,
                            const float* __restrict__ boxes,
                            const void*  __restrict__ ids,
                            const float* __restrict__ tbox,
                            float* __restrict__ C)
{
    __shared__ float4 s_tb[NT];
    __shared__ int    s_id[NT];
    __shared__ float  s_prob[QPB][NC];
    __shared__ float  s_box[QPB][4];

    const int tid = threadIdx.x;         // 128
    const int base_bq = blockIdx.x * QPB;
    const int mode = g_idmode;

    const float4* tb4 = (const float4*)tbox;
    for (int x = tid; x < NT; x += 128) s_tb[x] = tb4[x];
    if (mode) {
        const long long* id64 = (const long long*)ids;
        for (int x = tid; x < NT; x += 128) s_id[x] = (int)id64[x];
    } else {
        const int* id32 = (const int*)ids;
        for (int x = tid; x < NT; x += 128) s_id[x] = id32[x];
    }

    const int w = tid >> 5, lane = tid & 31;
    for (int r = w; r < QPB; r += 4) {
        int bq = base_bq + r;
        const float* lr = logits + (size_t)bq * NC;
        float x0 = lr[lane];
        float x1 = lr[lane + 32];
        float x2 = (lane + 64 < NC) ? lr[lane + 64] : -1e30f;
        float m = fmaxf(x0, fmaxf(x1, x2));
        for (int o = 16; o; o >>= 1) m = fmaxf(m, __shfl_xor_sync(~0u, m, o));
        float e0 = expf(x0 - m);
        float e1 = expf(x1 - m);
        float e2 = (lane + 64 < NC) ? expf(x2 - m) : 0.0f;
        float s = e0 + e1 + e2;
        for (int o = 16; o; o >>= 1) s += __shfl_xor_sync(~0u, s, o);
        float inv = 1.0f / s;
        s_prob[r][lane]      = e0 * inv;
        s_prob[r][lane + 32] = e1 * inv;
        if (lane + 64 < NC) s_prob[r][lane + 64] = e2 * inv;
        if (lane < 4) s_box[r][lane] = boxes[(size_t)bq * 4 + lane];
    }
    __syncthreads();

    for (int r = 0; r < QPB; r++) {
        const int bq = base_bq + r;
        const float pcx = s_box[r][0], pcy = s_box[r][1];
        const float pw  = s_box[r][2], ph  = s_box[r][3];
        const float px0 = pcx - pw * 0.5f, py0 = pcy - ph * 0.5f;
        const float px1 = pcx + pw * 0.5f, py1 = pcy + ph * 0.5f;
        const float pa  = (px1 - px0) * (py1 - py0);
        float* Crow = C + (size_t)bq * NT;
        for (int j = tid; j < NT; j += 128) {
            float4 t = s_tb[j];
            float tx0 = t.x, ty0 = t.y, tx1 = t.z, ty1 = t.w;
            float tcx = (tx0 + tx1) * 0.5f, tcy = (ty0 + ty1) * 0.5f;
            float tw = tx1 - tx0, th = ty1 - ty0;
            float cbb = fabsf(pcx - tcx) + fabsf(pcy - tcy)
                      + fabsf(pw - tw) + fabsf(ph - th);
            float ta = tw * th;
            float ix0 = fmaxf(px0, tx0), iy0 = fmaxf(py0, ty0);
            float ix1 = fminf(px1, tx1), iy1 = fminf(py1, ty1);
            float iw = fmaxf(ix1 - ix0, 0.0f), ih = fmaxf(iy1 - iy0, 0.0f);
            float inter = iw * ih;
            float uni = pa + ta - inter;
            float iou = inter / uni;
            float ex0 = fminf(px0, tx0), ey0 = fminf(py0, ty0);
            float ex1 = fmaxf(px1, tx1), ey1 = fmaxf(py1, ty1);
            float cw = fmaxf(ex1 - ex0, 0.0f), ch = fmaxf(ey1 - ey0, 0.0f);
            float ca = cw * ch;
            float giou = iou - (ca - uni) / ca;
            float val = 5.0f * cbb - s_prob[r][s_id[j]] - 2.0f * giou;
            Crow[j] = val;
        }
    }
}

// ---------------------------------------------------------------------------
// Transpose: C[b, q, b*T + t] -> g_ctr[b][t][q]
// ---------------------------------------------------------------------------
__global__ void transpose_kernel(const float* __restrict__ C)
{
    __shared__ float tile[32][33];
    float* g_ctrf = (float*)g_ctr4;
    const int b  = blockIdx.z;
    const int q0 = blockIdx.x * 32;
    const int t0 = blockIdx.y * 32;
    int q = q0 + threadIdx.y;
    int t = t0 + threadIdx.x;
    if (q < Q && t < TPB)
        tile[threadIdx.y][threadIdx.x] =
            C[((size_t)(b * Q + q)) * NT + (size_t)b * TPB + t];
    __syncthreads();
    int tt = t0 + threadIdx.y;
    int qq = q0 + threadIdx.x;
    if (tt < TPB && qq < Q)
        g_ctrf[b * (TPB * Q) + tt * Q + qq] = tile[threadIdx.x][threadIdx.y];
}

// ---------------------------------------------------------------------------
__device__ __forceinline__ unsigned long long enc64(double x)
{
    long long b = __double_as_longlong(x);
    if ((b << 1) == 0) b = 0;   // canonicalize -0.0 -> +0.0
    return (unsigned long long)(b ^ ((b >> 63) | 0x8000000000000000LL));
}
__device__ __forceinline__ double dec64(unsigned long long e)
{
    long long b = (long long)e;
    b ^= ((~b) >> 63) | 0x8000000000000000LL;
    return __longlong_as_double(b);
}

// ---------------------------------------------------------------------------
// Hungarian (JV), one block of 128 threads per batch.
// Columns per thread: group0 = 4*tid+{0..3}, group1 = 512+4*tid+{0..3} (tid<97).
// float4 loads; scan folded into post-reduce merge; REDUX hi-word fast path.
// One __syncthreads per inner iteration.
// ---------------------------------------------------------------------------
__global__ void __launch_bounds__(128, 1) lsa_kernel(float* __restrict__ out)
{
    const int b = blockIdx.x;
    const int tid = threadIdx.x;
    const int w = tid >> 5, lane = tid & 31;
    const bool g1ok = (tid < 97);

    __shared__ double u[TPB + 2];
    __shared__ int    p[Q + 2];
    __shared__ int    way[Q + 2];
    __shared__ unsigned long long s_em[2][4];
    __shared__ int    s_j[2][4];
    __shared__ int    s_p[2][4];
    __shared__ int    ans[TPB];

    double v[8];
    int rowof[8];
    int colv[8];
#pragma unroll
    for (int k = 0; k < 8; k++) {
        v[k] = 0.0; rowof[k] = 0;
        colv[k] = (k < 4) ? (4 * tid + k) : (512 + 4 * tid + (k - 4));
    }

    for (int x = tid; x <= Q; x += 128) p[x] = 0;
    if (tid <= TPB) u[tid] = 0.0;
    __syncthreads();

    const float4* cb4 = g_ctr4 + b * (TPB * ROW_F4);

    // prefetch round 1's row (row 0)
    float4 nxt0 = __ldg(&cb4[tid]);
    float4 nxt1 = g1ok ? __ldg(&cb4[128 + tid]) : make_float4(0.f,0.f,0.f,0.f);

    int par = 0;

    for (int i = 1; i <= TPB; i++) {
        if (tid == 0) p[0] = i;
        double minv[8];
        unsigned long long em[8];
        unsigned usedm = 0;

        // ---- first scan of row i (u[i]=0, minv=INF so every col wins) ----
        float rwf[8] = { nxt0.x, nxt0.y, nxt0.z, nxt0.w,
                         nxt1.x, nxt1.y, nxt1.z, nxt1.w };
        unsigned long long bestE = ~0ULL; int bestJ = Q + 2;
#pragma unroll
        for (int k = 0; k < 8; k++) {
            if (k < 4 || g1ok) {
                double cur = ((double)rwf[k] - 0.0) - v[k];
                minv[k] = cur; em[k] = enc64(cur); way[colv[k] + 1] = 0;
                if (em[k] < bestE) { bestE = em[k]; bestJ = colv[k] + 1; }
            } else { minv[k] = 1e300; em[k] = ~0ULL; }
        }

        // prefetch next round's first row
        if (i < TPB) {
            nxt0 = __ldg(&cb4[i * ROW_F4 + tid]);
            if (g1ok) nxt1 = __ldg(&cb4[i * ROW_F4 + 128 + tid]);
        }

        while (true) {
            // ---- warp argmin: hi-word REDUX fast path ----
            unsigned hi  = (unsigned)(bestE >> 32);
            unsigned mhi = __reduce_min_sync(0xffffffffu, hi);
            unsigned bal = __ballot_sync(0xffffffffu, hi == mhi);
            unsigned long long wem; int wj;
            if (__popc(bal) == 1) {
                int src = __ffs(bal) - 1;
                wem = __shfl_sync(0xffffffffu, bestE, src);
                wj  = __shfl_sync(0xffffffffu, bestJ, src);
            } else {
                unsigned lo  = (hi == mhi) ? (unsigned)bestE : 0xffffffffu;
                unsigned mlo = __reduce_min_sync(0xffffffffu, lo);
                unsigned cjj = (hi == mhi && (unsigned)bestE == mlo)
                               ? (unsigned)bestJ : 0x7fffffffu;
                unsigned mj  = __reduce_min_sync(0xffffffffu, cjj);
                wem = ((unsigned long long)mhi << 32) | mlo;
                wj  = (int)mj;
            }
            if (lane == 0) {
                s_em[par][w] = wem; s_j[par][w] = wj; s_p[par][w] = p[wj];
            }
            __syncthreads();                                   // ONE barrier

            unsigned long long ce0 = s_em[par][0], ce1 = s_em[par][1],
                               ce2 = s_em[par][2], ce3 = s_em[par][3];
            int cj0 = s_j[par][0], cj1 = s_j[par][1],
                cj2 = s_j[par][2], cj3 = s_j[par][3];
            int cp0 = s_p[par][0], cp1 = s_p[par][1],
                cp2 = s_p[par][2], cp3 = s_p[par][3];

            // issue candidate-row float4 prefetches immediately
            float4 ra0, rb0, ra1, rb1, ra2, rb2, ra3, rb3;
            if (cp0) { const float4* cr = cb4 + (cp0 - 1) * ROW_F4;
                ra0 = __ldg(&cr[tid]); if (g1ok) rb0 = __ldg(&cr[128 + tid]); }
            if (cp1) { const float4* cr = cb4 + (cp1 - 1) * ROW_F4;
                ra1 = __ldg(&cr[tid]); if (g1ok) rb1 = __ldg(&cr[128 + tid]); }
            if (cp2) { const float4* cr = cb4 + (cp2 - 1) * ROW_F4;
                ra2 = __ldg(&cr[tid]); if (g1ok) rb2 = __ldg(&cr[128 + tid]); }
            if (cp3) { const float4* cr = cb4 + (cp3 - 1) * ROW_F4;
                ra3 = __ldg(&cr[tid]); if (g1ok) rb3 = __ldg(&cr[128 + tid]); }

            // final 4-way reduce (ties -> smaller j); track winner warp
            unsigned long long de = ce0; int j1 = cj0, i1 = cp0, ww = 0;
            if (ce1 < de || (ce1 == de && cj1 < j1)) { de = ce1; j1 = cj1; i1 = cp1; ww = 1; }
            if (ce2 < de || (ce2 == de && cj2 < j1)) { de = ce2; j1 = cj2; i1 = cp2; ww = 2; }
            if (ce3 < de || (ce3 == de && cj3 < j1)) { de = ce3; j1 = cj3; i1 = cp3; ww = 3; }
            const double delta = dec64(de);
            const double ui1 = (i1 != 0) ? u[i1] : 0.0;  // row i1 untouched this iter

            // dual updates (reference order; exact fp64)
#pragma unroll
            for (int k = 0; k < 8; k++) {
                if (k < 4 || g1ok) {
                    if ((usedm >> k) & 1u) { v[k] -= delta; u[rowof[k]] += delta; }
                    else {
                        minv[k] -= delta;
                        em[k] = enc64(minv[k]);
                    }
                }
            }
            if (tid == 0) u[i] += delta;   // virtual column 0 (row i)

            if (i1 == 0) {
                if (tid == 0) {
                    int jj = j1;
                    while (jj) { int jp = way[jj]; p[jj] = p[jp]; jj = jp; }
                }
                par ^= 1;
                break;
            }

            // mark j1 used (owner thread)
            {
                int c = j1 - 1, og, okk;
                if (c < 512) { og = c >> 2;        okk = c & 3; }
                else         { og = (c - 512) >> 2; okk = 4 + ((c - 512) & 3); }
                if (og == tid) { usedm |= 1u << okk; rowof[okk] = i1; }
            }

            // select winner row registers
            float4 wa = ra0, wb = rb0;
            if (ww == 1) { wa = ra1; wb = rb1; }
            if (ww == 2) { wa = ra2; wb = rb2; }
            if (ww == 3) { wa = ra3; wb = rb3; }
            rwf[0] = wa.x; rwf[1] = wa.y; rwf[2] = wa.z; rwf[3] = wa.w;
            rwf[4] = wb.x; rwf[5] = wb.y; rwf[6] = wb.z; rwf[7] = wb.w;

            // merge winner row's cur into minv/em (== reference's next scan),
            // and recompute warp-local best
            bestE = ~0ULL; bestJ = Q + 2;
#pragma unroll
            for (int k = 0; k < 8; k++) {
                if ((k < 4 || g1ok) && !((usedm >> k) & 1u)) {
                    double cur = ((double)rwf[k] - ui1) - v[k];
                    unsigned long long ec = enc64(cur);
                    if (ec < em[k]) { em[k] = ec; minv[k] = cur; way[colv[k] + 1] = j1; }
                    if (em[k] < bestE) { bestE = em[k]; bestJ = colv[k] + 1; }
                }
            }
            par ^= 1;
        }
        __syncthreads();   // p[] path-walk visible before next round / epilogue
    }

    // ans[t] = matched prediction index for target t
#pragma unroll
    for (int k = 0; k < 8; k++) {
        if (k < 4 || g1ok) {
            int j = colv[k] + 1;
            if (p[j] > 0) ans[p[j] - 1] = j - 1;
        }
    }
    __syncthreads();
    if (tid < TPB) {
        int a = ans[tid];
        int rank = 0;
        for (int t2 = 0; t2 < TPB; t2++) rank += (ans[t2] < a) ? 1 : 0;
        out[(size_t)C_ELEMS + (size_t)b * TPB + rank]                    = (float)a;
        out[(size_t)C_ELEMS + (size_t)BS * TPB + (size_t)b * TPB + rank] = (float)tid;
    }
}

// ---------------------------------------------------------------------------
extern "C" void kernel_launch(void* const* d_in, const int* in_sizes, int n_in,
                              void* d_out, int out_size)
{
    const float* logits = (const float*)d_in[0];
    const float* boxes  = (const float*)d_in[1];
    const void*  ids    = d_in[2];
    const float* tbox   = (const float*)d_in[3];
    float* out = (float*)d_out;

    detect_ids_kernel<<<1, 128>>>((const unsigned int*)ids);
    cost_kernel<<<(BS * Q) / QPB, 128>>>(logits, boxes, ids, tbox, out);
    dim3 tgrid((Q + 31) / 32, (TPB + 31) / 32, BS);
    transpose_kernel<<<tgrid, dim3(32, 32)>>>(out);
    lsa_kernel<<<BS, 128>>>(out);
}

// round 8
// speedup vs baseline: 1.7356x; 1.3838x over previous
#include <cuda_runtime.h>
#include <cuda_bf16.h>
#include <math.h>

#define BS 16
#define Q 900
#define NC 92
#define TPB 100          // targets per batch
#define NT 1600          // total targets
#define C_ELEMS (16*900*1600)  // 23040000
#define ROW_F4 (Q/4)     // 225 float4 per row

// transposed per-batch cost slice, 16B-aligned for float4 loads
__device__ float4 g_ctr4[BS * TPB * ROW_F4];
__device__ int    g_idmode;

// ---------------------------------------------------------------------------
__global__ void detect_ids_kernel(const unsigned int* __restrict__ ids)
{
    const int tid = threadIdx.x;  // 128
    int ok = 1;
    for (int k = tid; k < 800; k += 128) {
        unsigned lo = ids[2*k], hi = ids[2*k+1];
        if (hi != 0u || lo >= 92u) ok = 0;
    }
    ok = __syncthreads_and(ok);
    if (tid == 0) g_idmode = ok;
}

// ---------------------------------------------------------------------------
#define QPB 8
__global__ void cost_kernel(const float* __restrict__ logits,
                            const float* __restrict__ boxes,
                            const void*  __restrict__ ids,
                            const float* __restrict__ tbox,
                            float* __restrict__ C)
{
    __shared__ float4 s_tb[NT];
    __shared__ int    s_id[NT];
    __shared__ float  s_prob[QPB][NC];
    __shared__ float  s_box[QPB][4];

    const int tid = threadIdx.x;         // 128
    const int base_bq = blockIdx.x * QPB;
    const int mode = g_idmode;

    const float4* tb4 = (const float4*)tbox;
    for (int x = tid; x < NT; x += 128) s_tb[x] = tb4[x];
    if (mode) {
        const long long* id64 = (const long long*)ids;
        for (int x = tid; x < NT; x += 128) s_id[x] = (int)id64[x];
    } else {
        const int* id32 = (const int*)ids;
        for (int x = tid; x < NT; x += 128) s_id[x] = id32[x];
    }

    const int w = tid >> 5, lane = tid & 31;
    for (int r = w; r < QPB; r += 4) {
        int bq = base_bq + r;
        const float* lr = logits + (size_t)bq * NC;
        float x0 = lr[lane];
        float x1 = lr[lane + 32];
        float x2 = (lane + 64 < NC) ? lr[lane + 64] : -1e30f;
        float m = fmaxf(x0, fmaxf(x1, x2));
        for (int o = 16; o; o >>= 1) m = fmaxf(m, __shfl_xor_sync(~0u, m, o));
        float e0 = expf(x0 - m);
        float e1 = expf(x1 - m);
        float e2 = (lane + 64 < NC) ? expf(x2 - m) : 0.0f;
        float s = e0 + e1 + e2;
        for (int o = 16; o; o >>= 1) s += __shfl_xor_sync(~0u, s, o);
        float inv = 1.0f / s;
        s_prob[r][lane]      = e0 * inv;
        s_prob[r][lane + 32] = e1 * inv;
        if (lane + 64 < NC) s_prob[r][lane + 64] = e2 * inv;
        if (lane < 4) s_box[r][lane] = boxes[(size_t)bq * 4 + lane];
    }
    __syncthreads();

    for (int r = 0; r < QPB; r++) {
        const int bq = base_bq + r;
        const float pcx = s_box[r][0], pcy = s_box[r][1];
        const float pw  = s_box[r][2], ph  = s_box[r][3];
        const float px0 = pcx - pw * 0.5f, py0 = pcy - ph * 0.5f;
        const float px1 = pcx + pw * 0.5f, py1 = pcy + ph * 0.5f;
        const float pa  = (px1 - px0) * (py1 - py0);
        float* Crow = C + (size_t)bq * NT;
        for (int j = tid; j < NT; j += 128) {
            float4 t = s_tb[j];
            float tx0 = t.x, ty0 = t.y, tx1 = t.z, ty1 = t.w;
            float tcx = (tx0 + tx1) * 0.5f, tcy = (ty0 + ty1) * 0.5f;
            float tw = tx1 - tx0, th = ty1 - ty0;
            float cbb = fabsf(pcx - tcx) + fabsf(pcy - tcy)
                      + fabsf(pw - tw) + fabsf(ph - th);
            float ta = tw * th;
            float ix0 = fmaxf(px0, tx0), iy0 = fmaxf(py0, ty0);
            float ix1 = fminf(px1, tx1), iy1 = fminf(py1, ty1);
            float iw = fmaxf(ix1 - ix0, 0.0f), ih = fmaxf(iy1 - iy0, 0.0f);
            float inter = iw * ih;
            float uni = pa + ta - inter;
            float iou = inter / uni;
            float ex0 = fminf(px0, tx0), ey0 = fminf(py0, ty0);
            float ex1 = fmaxf(px1, tx1), ey1 = fmaxf(py1, ty1);
            float cw = fmaxf(ex1 - ex0, 0.0f), ch = fmaxf(ey1 - ey0, 0.0f);
            float ca = cw * ch;
            float giou = iou - (ca - uni) / ca;
            float val = 5.0f * cbb - s_prob[r][s_id[j]] - 2.0f * giou;
            Crow[j] = val;
        }
    }
}

// ---------------------------------------------------------------------------
__global__ void transpose_kernel(const float* __restrict__ C)
{
    __shared__ float tile[32][33];
    float* g_ctrf = (float*)g_ctr4;
    const int b  = blockIdx.z;
    const int q0 = blockIdx.x * 32;
    const int t0 = blockIdx.y * 32;
    int q = q0 + threadIdx.y;
    int t = t0 + threadIdx.x;
    if (q < Q && t < TPB)
        tile[threadIdx.y][threadIdx.x] =
            C[((size_t)(b * Q + q)) * NT + (size_t)b * TPB + t];
    __syncthreads();
    int tt = t0 + threadIdx.y;
    int qq = q0 + threadIdx.x;
    if (tt < TPB && qq < Q)
        g_ctrf[b * (TPB * Q) + tt * Q + qq] = tile[threadIdx.x][threadIdx.y];
}

// ---------------------------------------------------------------------------
// Order-preserving double <-> uint64 encoding (ascending).
// -0.0 canonicalization omitted: every compared value here is produced by an
// RN-mode subtraction (cannot yield -0 given the operand provenance), so -0
// never reaches a comparison.
// ---------------------------------------------------------------------------
__device__ __forceinline__ unsigned long long enc64(double x)
{
    long long b = __double_as_longlong(x);
    return (unsigned long long)(b ^ ((b >> 63) | 0x8000000000000000LL));
}
__device__ __forceinline__ double dec64(unsigned long long e)
{
    long long b = (long long)e;
    b ^= ((~b) >> 63) | 0x8000000000000000LL;
    return __longlong_as_double(b);
}

// ---------------------------------------------------------------------------
// Hungarian (JV), one block of 128 threads per batch.
// Columns per thread: group0 = 4*tid+{0..3}, group1 = 512+4*tid+{0..3} (tid<97).
// Winner-lane direct STS, pre-barrier own-candidate prefetch, fused
// update+merge loop. j1's duals are updated one iteration LATER (matching the
// reference's used[j0]=True-at-top ordering). One __syncthreads per iteration.
// ---------------------------------------------------------------------------
__global__ void __launch_bounds__(128, 1) lsa_kernel(float* __restrict__ out)
{
    const int b = blockIdx.x;
    const int tid = threadIdx.x;
    const int w = tid >> 5, lane = tid & 31;
    const bool g1ok = (tid < 97);

    __shared__ double u[TPB + 2];
    __shared__ int    p[Q + 2];
    __shared__ int    way[Q + 2];
    __shared__ unsigned long long s_em[2][4];
    __shared__ int    s_j[2][4];
    __shared__ int    s_p[2][4];
    __shared__ int    ans[TPB];

    double v[8];
    int rowof[8];
    int colv[8];
#pragma unroll
    for (int k = 0; k < 8; k++) {
        v[k] = 0.0; rowof[k] = 0;
        colv[k] = (k < 4) ? (4 * tid + k) : (512 + 4 * tid + (k - 4));
    }

    for (int x = tid; x <= Q; x += 128) p[x] = 0;
    if (tid <= TPB) u[tid] = 0.0;
    __syncthreads();

    const float4* cb4 = g_ctr4 + b * (TPB * ROW_F4);

    // prefetch round 1's row (row 0)
    float4 nxt0 = __ldg(&cb4[tid]);
    float4 nxt1 = g1ok ? __ldg(&cb4[128 + tid]) : make_float4(0.f,0.f,0.f,0.f);

    int par = 0;

    for (int i = 1; i <= TPB; i++) {
        if (tid == 0) p[0] = i;
        double minv[8];
        unsigned long long em[8];
        unsigned usedm = 0;

        // ---- first scan of row i (u[i]=0, minv=INF so every col wins) ----
        float rwf[8] = { nxt0.x, nxt0.y, nxt0.z, nxt0.w,
                         nxt1.x, nxt1.y, nxt1.z, nxt1.w };
        unsigned long long bestE = ~0ULL; int bestJ = Q + 2;
#pragma unroll
        for (int k = 0; k < 8; k++) {
            if (k < 4 || g1ok) {
                double cur = ((double)rwf[k] - 0.0) - v[k];
                minv[k] = cur; em[k] = enc64(cur); way[colv[k] + 1] = 0;
                if (em[k] < bestE) { bestE = em[k]; bestJ = colv[k] + 1; }
            } else { minv[k] = 1e300; em[k] = ~0ULL; }
        }

        // prefetch next round's first row
        if (i < TPB) {
            nxt0 = __ldg(&cb4[i * ROW_F4 + tid]);
            if (g1ok) nxt1 = __ldg(&cb4[i * ROW_F4 + 128 + tid]);
        }

        while (true) {
            // ---- warp argmin; winner lane writes SMEM directly ----
            unsigned hi  = (unsigned)(bestE >> 32);
            unsigned mhi = __reduce_min_sync(0xffffffffu, hi);
            unsigned bal = __ballot_sync(0xffffffffu, hi == mhi);
            int srcJ;
            if (__popc(bal) == 1) {
                int src = __ffs(bal) - 1;
                if (lane == src) { s_em[par][w] = bestE; s_j[par][w] = bestJ; }
                srcJ = __shfl_sync(0xffffffffu, bestJ, src);
            } else {
                unsigned lo  = (hi == mhi) ? (unsigned)bestE : 0xffffffffu;
                unsigned mlo = __reduce_min_sync(0xffffffffu, lo);
                unsigned cjj = (hi == mhi && (unsigned)bestE == mlo)
                               ? (unsigned)bestJ : 0x7fffffffu;
                unsigned mj  = __reduce_min_sync(0xffffffffu, cjj);
                // bestJ values are distinct across lanes -> unique writer
                if ((unsigned)bestJ == mj) {
                    s_em[par][w] = ((unsigned long long)mhi << 32) | mlo;
                    s_j[par][w]  = mj;
                }
                srcJ = (int)mj;
            }
            const int wp = p[srcJ];           // broadcast LDS (same addr per warp)
            if (lane == 0) s_p[par][w] = wp;

            // pre-barrier prefetch of OWN warp's candidate row
            float4 own0, own1;
            own0 = make_float4(0.f,0.f,0.f,0.f); own1 = own0;
            if (wp) {
                const float4* cr = cb4 + (wp - 1) * ROW_F4;
                own0 = __ldg(&cr[tid]);
                if (g1ok) own1 = __ldg(&cr[128 + tid]);
            }
            __syncthreads();                                   // ONE barrier

            unsigned long long ce0 = s_em[par][0], ce1 = s_em[par][1],
                               ce2 = s_em[par][2], ce3 = s_em[par][3];
            int cj0 = s_j[par][0], cj1 = s_j[par][1],
                cj2 = s_j[par][2], cj3 = s_j[par][3];
            int cp0 = s_p[par][0], cp1 = s_p[par][1],
                cp2 = s_p[par][2], cp3 = s_p[par][3];

            // prefetch the other 3 warps' candidate rows (own slot = own regs)
            float4 ra0, rb0, ra1, rb1, ra2, rb2, ra3, rb3;
            if (w == 0) { ra0 = own0; rb0 = own1; }
            else if (cp0) { const float4* cr = cb4 + (cp0 - 1) * ROW_F4;
                ra0 = __ldg(&cr[tid]); if (g1ok) rb0 = __ldg(&cr[128 + tid]); }
            if (w == 1) { ra1 = own0; rb1 = own1; }
            else if (cp1) { const float4* cr = cb4 + (cp1 - 1) * ROW_F4;
                ra1 = __ldg(&cr[tid]); if (g1ok) rb1 = __ldg(&cr[128 + tid]); }
            if (w == 2) { ra2 = own0; rb2 = own1; }
            else if (cp2) { const float4* cr = cb4 + (cp2 - 1) * ROW_F4;
                ra2 = __ldg(&cr[tid]); if (g1ok) rb2 = __ldg(&cr[128 + tid]); }
            if (w == 3) { ra3 = own0; rb3 = own1; }
            else if (cp3) { const float4* cr = cb4 + (cp3 - 1) * ROW_F4;
                ra3 = __ldg(&cr[tid]); if (g1ok) rb3 = __ldg(&cr[128 + tid]); }

            // final 4-way reduce (ties -> smaller j); track winner warp
            unsigned long long de = ce0; int j1 = cj0, i1 = cp0, ww = 0;
            if (ce1 < de || (ce1 == de && cj1 < j1)) { de = ce1; j1 = cj1; i1 = cp1; ww = 1; }
            if (ce2 < de || (ce2 == de && cj2 < j1)) { de = ce2; j1 = cj2; i1 = cp2; ww = 2; }
            if (ce3 < de || (ce3 == de && cj3 < j1)) { de = ce3; j1 = cj3; i1 = cp3; ww = 3; }
            const double delta = dec64(de);

            if (i1 == 0) {
                // augmentation ends: minv dead; used-only dual updates persist.
                // (j1 itself never joins used: reference's update at this pass
                // uses used = {0, prior columns}.)
#pragma unroll
                for (int k = 0; k < 8; k++) {
                    if ((k < 4 || g1ok) && ((usedm >> k) & 1u)) {
                        v[k] -= delta; u[rowof[k]] += delta;
                    }
                }
                if (tid == 0) {
                    u[i] += delta;
                    int jj = j1;
                    while (jj) { int jp = way[jj]; p[jj] = p[jp]; jj = jp; }
                }
                par ^= 1;
                break;
            }

            const double ui1 = u[i1];   // row i1 untouched this iteration

            // select winner row registers
            float4 wa = ra0, wb = rb0;
            if (ww == 1) { wa = ra1; wb = rb1; }
            if (ww == 2) { wa = ra2; wb = rb2; }
            if (ww == 3) { wa = ra3; wb = rb3; }
            rwf[0] = wa.x; rwf[1] = wa.y; rwf[2] = wa.z; rwf[3] = wa.w;
            rwf[4] = wb.x; rwf[5] = wb.y; rwf[6] = wb.z; rwf[7] = wb.w;

            // FUSED update + merge with the OLD used mask (j1 NOT included:
            // its v/u updates belong to the NEXT pass, per the reference's
            // used[j0]=True-at-top ordering). j1 is skipped in the merge (its
            // minv is decremented in the reference but never read again).
            bestE = ~0ULL; bestJ = Q + 2;
#pragma unroll
            for (int k = 0; k < 8; k++) {
                if (k < 4 || g1ok) {
                    if ((usedm >> k) & 1u) {
                        v[k] -= delta; u[rowof[k]] += delta;
                    } else if (colv[k] + 1 != j1) {
                        double m2  = minv[k] - delta;
                        double cur = ((double)rwf[k] - ui1) - v[k];
                        unsigned long long e2 = enc64(m2);
                        unsigned long long ec = enc64(cur);
                        if (ec < e2) { minv[k] = cur; em[k] = ec; way[colv[k] + 1] = j1; }
                        else         { minv[k] = m2;  em[k] = e2; }
                        if (em[k] < bestE) { bestE = em[k]; bestJ = colv[k] + 1; }
                    }
                }
            }
            if (tid == 0) u[i] += delta;   // virtual column 0 (row i)

            // NOW mark j1 used for subsequent iterations (owner thread)
            {
                int c = j1 - 1, og, okk;
                if (c < 512) { og = c >> 2;        okk = c & 3; }
                else         { og = (c - 512) >> 2; okk = 4 + ((c - 512) & 3); }
                if (og == tid) { usedm |= 1u << okk; rowof[okk] = i1; }
            }
            par ^= 1;
        }
        __syncthreads();   // p[] / u[] writes visible before next round
    }

    // ans[t] = matched prediction index for target t
#pragma unroll
    for (int k = 0; k < 8; k++) {
        if (k < 4 || g1ok) {
            int j = colv[k] + 1;
            if (p[j] > 0) ans[p[j] - 1] = j - 1;
        }
    }
    __syncthreads();
    if (tid < TPB) {
        int a = ans[tid];
        int rank = 0;
        for (int t2 = 0; t2 < TPB; t2++) rank += (ans[t2] < a) ? 1 : 0;
        out[(size_t)C_ELEMS + (size_t)b * TPB + rank]                    = (float)a;
        out[(size_t)C_ELEMS + (size_t)BS * TPB + (size_t)b * TPB + rank] = (float)tid;
    }
}

// ---------------------------------------------------------------------------
extern "C" void kernel_launch(void* const* d_in, const int* in_sizes, int n_in,
                              void* d_out, int out_size)
{
    const float* logits = (const float*)d_in[0];
    const float* boxes  = (const float*)d_in[1];
    const void*  ids    = d_in[2];
    const float* tbox   = (const float*)d_in[3];
    float* out = (float*)d_out;

    detect_ids_kernel<<<1, 128>>>((const unsigned int*)ids);
    cost_kernel<<<(BS * Q) / QPB, 128>>>(logits, boxes, ids, tbox, out);
    dim3 tgrid((Q + 31) / 32, (TPB + 31) / 32, BS);
    transpose_kernel<<<tgrid, dim3(32, 32)>>>(out);
    lsa_kernel<<<BS, 128>>>(out);
}